// round 1
// baseline (speedup 1.0000x reference)
#include <cuda_runtime.h>

#define T_SEQ   2048
#define HEADS   16
#define GROUPS  4
#define D_HEAD  128
#define TK_     (T_SEQ + 1)
#define QKV_DIM 3072
#define C_DIM   2048
#define SCALE_Q 0.08838834764831845f   // 1/sqrt(128)

// ---------------- scratch (device globals; no allocation allowed) ----------
__device__ float g_qkv[T_SEQ * QKV_DIM];            // 25.2 MB
__device__ float g_Q  [T_SEQ * HEADS * D_HEAD];     // 16.8 MB (rope'd, pre-scaled)
__device__ float g_K  [GROUPS * TK_ * D_HEAD];      // 4.2 MB  ([g][j][d], j=0 sink)
__device__ float g_V  [GROUPS * TK_ * D_HEAD];      // 4.2 MB
__device__ float g_O  [T_SEQ * HEADS * D_HEAD];     // 16.8 MB

// ---------------- SGEMM NT: C[m,n] = sum_k A[m,k]*B[n,k] --------------------
// BM=BN=128, BK=8, 256 threads, 8x8 per-thread microkernel.
__device__ __forceinline__ void sgemm_nt_body(
    const float* __restrict__ A, const float* __restrict__ B,
    float* __restrict__ C, int N, int K)
{
    __shared__ float As[8][128];
    __shared__ float Bs[8][128];
    const int tid = threadIdx.x;
    const int tx  = tid & 15;
    const int ty  = tid >> 4;
    const int row = tid >> 1;          // 0..127
    const int col = (tid & 1) << 2;    // 0 or 4

    const float* Ab = A + (blockIdx.y * 128 + row) * K + col;
    const float* Bb = B + (blockIdx.x * 128 + row) * K + col;

    float acc[8][8] = {};

    for (int k0 = 0; k0 < K; k0 += 8) {
        float4 a4 = *(const float4*)(Ab + k0);
        float4 b4 = *(const float4*)(Bb + k0);
        As[col+0][row] = a4.x; As[col+1][row] = a4.y;
        As[col+2][row] = a4.z; As[col+3][row] = a4.w;
        Bs[col+0][row] = b4.x; Bs[col+1][row] = b4.y;
        Bs[col+2][row] = b4.z; Bs[col+3][row] = b4.w;
        __syncthreads();
        #pragma unroll
        for (int k = 0; k < 8; ++k) {
            float ra[8], rb[8];
            *(float4*)&ra[0] = *(const float4*)&As[k][ty*8];
            *(float4*)&ra[4] = *(const float4*)&As[k][ty*8+4];
            *(float4*)&rb[0] = *(const float4*)&Bs[k][tx*8];
            *(float4*)&rb[4] = *(const float4*)&Bs[k][tx*8+4];
            #pragma unroll
            for (int i = 0; i < 8; ++i)
                #pragma unroll
                for (int j = 0; j < 8; ++j)
                    acc[i][j] += ra[i] * rb[j];
        }
        __syncthreads();
    }

    float* Cb = C + (blockIdx.y*128 + ty*8) * N + blockIdx.x*128 + tx*8;
    #pragma unroll
    for (int i = 0; i < 8; ++i) {
        *(float4*)(Cb + i*N)     = make_float4(acc[i][0],acc[i][1],acc[i][2],acc[i][3]);
        *(float4*)(Cb + i*N + 4) = make_float4(acc[i][4],acc[i][5],acc[i][6],acc[i][7]);
    }
}

__global__ void __launch_bounds__(256)
k_qkv_gemm(const float* __restrict__ x, const float* __restrict__ W_attn)
{
    sgemm_nt_body(x, W_attn, g_qkv, QKV_DIM, C_DIM);
}

__global__ void __launch_bounds__(256)
k_proj_gemm(const float* __restrict__ W_proj, float* __restrict__ out)
{
    sgemm_nt_body(g_O, W_proj, out, C_DIM, HEADS * D_HEAD);
}

// ---------------- RoPE + scatter -------------------------------------------
// qkv layout: [t][g][s][d] with s in {0..3:q, 4:k, 5:v}, d=128, g=4.
__global__ void __launch_bounds__(256)
k_rope_q(const float* __restrict__ cosb, const float* __restrict__ sinb)
{
    int idx = blockIdx.x * blockDim.x + threadIdx.x;   // T*H*64
    int j = idx & 63;
    int h = (idx >> 6) & 15;
    int t = idx >> 10;
    const float* base = g_qkv + t*QKV_DIM + (h >> 2)*768 + (h & 3)*128;
    float x1 = base[j], x2 = base[64 + j];
    float c = cosb[t*64 + j], s = sinb[t*64 + j];
    float* q = g_Q + (t*HEADS + h)*D_HEAD;
    q[j]      = (x1*c - x2*s) * SCALE_Q;
    q[64 + j] = (x1*s + x2*c) * SCALE_Q;
}

__global__ void __launch_bounds__(256)
k_rope_k(const float* __restrict__ cosb, const float* __restrict__ sinb)
{
    int idx = blockIdx.x * blockDim.x + threadIdx.x;   // T*G*64
    int j = idx & 63;
    int g = (idx >> 6) & 3;
    int t = idx >> 8;
    const float* base = g_qkv + t*QKV_DIM + g*768 + 512;
    float x1 = base[j], x2 = base[64 + j];
    float c = cosb[t*64 + j], s = sinb[t*64 + j];
    float* k = g_K + (g*TK_ + t + 1)*D_HEAD;
    k[j]      = x1*c - x2*s;
    k[64 + j] = x1*s + x2*c;
}

__global__ void __launch_bounds__(256)
k_copy_v()
{
    int idx = blockIdx.x * blockDim.x + threadIdx.x;   // T*G*128
    int d = idx & 127;
    int g = (idx >> 7) & 3;
    int t = idx >> 9;
    g_V[(g*TK_ + t + 1)*D_HEAD + d] = g_qkv[t*QKV_DIM + g*768 + 640 + d];
}

__global__ void __launch_bounds__(256)
k_sink(const float* __restrict__ k_sink, const float* __restrict__ v_sink)
{
    int idx = blockIdx.x * blockDim.x + threadIdx.x;   // G*128 = 512
    if (idx >= GROUPS * D_HEAD) return;
    int g = idx >> 7;
    int d = idx & 127;
    g_K[(g*TK_)*D_HEAD + d] = k_sink[idx];
    g_V[(g*TK_)*D_HEAD + d] = v_sink[idx];
}

// ---------------- attention -------------------------------------------------
// One block per (head, 64-query tile). 256 threads: each thread owns
// (query qi = tid>>2, interleaved quarter of D: dims 4*dd + (tid&3)).
// Quad shuffle combines partial dot products. Online softmax.
// Window: key j (j=0 sink) allowed iff  max(0, i-1022) <= j <= i+1.
#define KCHUNK 32
__global__ void __launch_bounds__(256)
k_attn()
{
    __shared__ float Ks[KCHUNK][D_HEAD];
    __shared__ float Vs[KCHUNK][D_HEAD];

    const int h  = blockIdx.y;
    const int g  = h >> 2;
    const int i0 = blockIdx.x * 64;
    const int tid = threadIdx.x;
    const int qi  = tid >> 2;
    const int q4  = tid & 3;         // dim phase: d = 4*dd + q4
    const int i   = i0 + qi;

    float qreg[32];
    {
        const float* qp = g_Q + (i*HEADS + h)*D_HEAD + q4;
        #pragma unroll
        for (int dd = 0; dd < 32; ++dd) qreg[dd] = qp[4*dd];
    }

    float acc[32] = {};
    float m = __int_as_float(0xff800000);   // -inf
    float l = 0.f;

    const int lo  = max(0, i - 1022);
    const int hi  = i + 1;                   // inclusive
    const int jlo = max(0, i0 - 1022);
    const int jhi = i0 + 64;                 // inclusive (max hi in tile)

    const float* Kg = g_K + g*TK_*D_HEAD;
    const float* Vg = g_V + g*TK_*D_HEAD;

    for (int j0 = jlo; j0 <= jhi; j0 += KCHUNK) {
        const int jn = min(KCHUNK, jhi + 1 - j0);
        __syncthreads();
        for (int e = tid; e < jn * 32; e += 256) {
            int r = e >> 5, c = e & 31;
            ((float4*)&Ks[r][0])[c] = ((const float4*)(Kg + (j0 + r)*D_HEAD))[c];
            ((float4*)&Vs[r][0])[c] = ((const float4*)(Vg + (j0 + r)*D_HEAD))[c];
        }
        __syncthreads();

        for (int jj = 0; jj < jn; ++jj) {
            const int j = j0 + jj;
            float s = 0.f;
            const float* kr = &Ks[jj][q4];
            #pragma unroll
            for (int dd = 0; dd < 32; ++dd) s += qreg[dd] * kr[4*dd];
            s += __shfl_xor_sync(0xffffffffu, s, 1);
            s += __shfl_xor_sync(0xffffffffu, s, 2);

            if (j < lo || j > hi) continue;

            if (s > m) {
                float corr = __expf(m - s);
                l *= corr;
                #pragma unroll
                for (int dd = 0; dd < 32; ++dd) acc[dd] *= corr;
                m = s;
            }
            float p = __expf(s - m);
            l += p;
            const float* vr = &Vs[jj][q4];
            #pragma unroll
            for (int dd = 0; dd < 32; ++dd) acc[dd] += p * vr[4*dd];
        }
    }

    const float inv = 1.f / l;
    float* op = g_O + (i*HEADS + h)*D_HEAD + q4;
    #pragma unroll
    for (int dd = 0; dd < 32; ++dd) op[4*dd] = acc[dd] * inv;
}

// ---------------- launch -----------------------------------------------------
extern "C" void kernel_launch(void* const* d_in, const int* in_sizes, int n_in,
                              void* d_out, int out_size)
{
    const float* x      = (const float*)d_in[0];
    const float* cosb   = (const float*)d_in[1];
    const float* sinb   = (const float*)d_in[2];
    const float* W_attn = (const float*)d_in[3];
    const float* W_proj = (const float*)d_in[4];
    const float* ksink  = (const float*)d_in[5];
    const float* vsink  = (const float*)d_in[6];
    float* out = (float*)d_out;

    // 1) qkv = x @ W_attn^T   (2048 x 3072, K=2048)
    k_qkv_gemm<<<dim3(QKV_DIM/128, T_SEQ/128), 256>>>(x, W_attn);

    // 2) RoPE + scatter (Q pre-scaled by 1/sqrt(D)); K/V with sink at j=0
    k_rope_q<<<(T_SEQ*HEADS*64)/256, 256>>>(cosb, sinb);
    k_rope_k<<<(T_SEQ*GROUPS*64)/256, 256>>>(cosb, sinb);
    k_copy_v<<<(T_SEQ*GROUPS*128)/256, 256>>>();
    k_sink<<<2, 256>>>(ksink, vsink);

    // 3) attention
    k_attn<<<dim3(T_SEQ/64, HEADS), 256>>>();

    // 4) y = o @ W_proj^T   (2048 x 2048, K=2048)
    k_proj_gemm<<<dim3(C_DIM/128, T_SEQ/128), 256>>>(W_proj, out);
}

// round 3
// speedup vs baseline: 1.4879x; 1.4879x over previous
#include <cuda_runtime.h>
#include <cuda_bf16.h>
#include <cstdint>

#define T_SEQ   2048
#define HEADS   16
#define GROUPS  4
#define D_HEAD  128
#define TK_     (T_SEQ + 1)
#define QKV_DIM 3072
#define C_DIM   2048
#define SCALE_Q 0.08838834764831845f   // 1/sqrt(128)

// ---------------- scratch (device globals; no allocation allowed) ----------
__device__ float g_qkv[T_SEQ * QKV_DIM];
__device__ float g_Q  [T_SEQ * HEADS * D_HEAD];
__device__ float g_K  [GROUPS * TK_ * D_HEAD];
__device__ float g_V  [GROUPS * TK_ * D_HEAD];
__device__ float g_O  [T_SEQ * HEADS * D_HEAD];

// bf16 hi/lo split operands for tensor-core GEMMs
__device__ __align__(16) __nv_bfloat16 g_xh [C_DIM  * C_DIM];
__device__ __align__(16) __nv_bfloat16 g_xl [C_DIM  * C_DIM];
__device__ __align__(16) __nv_bfloat16 g_wah[QKV_DIM * C_DIM];
__device__ __align__(16) __nv_bfloat16 g_wal[QKV_DIM * C_DIM];
__device__ __align__(16) __nv_bfloat16 g_oh [T_SEQ * HEADS * D_HEAD];
__device__ __align__(16) __nv_bfloat16 g_ol [T_SEQ * HEADS * D_HEAD];
__device__ __align__(16) __nv_bfloat16 g_wph[C_DIM * HEADS * D_HEAD];
__device__ __align__(16) __nv_bfloat16 g_wpl[C_DIM * HEADS * D_HEAD];

// ---------------- low-level helpers -----------------------------------------
__device__ __forceinline__ uint32_t smem_u32(const void* p) {
    uint32_t a;
    asm("{ .reg .u64 t; cvta.to.shared.u64 t, %1; cvt.u32.u64 %0, t; }" : "=r"(a) : "l"(p));
    return a;
}
#define CP_ASYNC16(sm, gp) \
    asm volatile("cp.async.cg.shared.global [%0], [%1], 16;" :: "r"(sm), "l"(gp) : "memory")
#define CP_COMMIT() asm volatile("cp.async.commit_group;" ::: "memory")
#define CP_WAIT(n)  asm volatile("cp.async.wait_group %0;" :: "n"(n) : "memory")

#define LDMATRIX_X4(r, a) \
    asm volatile("ldmatrix.sync.aligned.m8n8.x4.shared.b16 {%0,%1,%2,%3}, [%4];" \
        : "=r"((r)[0]), "=r"((r)[1]), "=r"((r)[2]), "=r"((r)[3]) : "r"(a))
#define LDMATRIX_X2(r, a) \
    asm volatile("ldmatrix.sync.aligned.m8n8.x2.shared.b16 {%0,%1}, [%2];" \
        : "=r"((r)[0]), "=r"((r)[1]) : "r"(a))

#define MMA_BF16(d, a, b) \
    asm volatile("mma.sync.aligned.m16n8k16.row.col.f32.bf16.bf16.f32 " \
        "{%0,%1,%2,%3},{%4,%5,%6,%7},{%8,%9},{%0,%1,%2,%3};" \
        : "+f"((d)[0]), "+f"((d)[1]), "+f"((d)[2]), "+f"((d)[3]) \
        : "r"((a)[0]), "r"((a)[1]), "r"((a)[2]), "r"((a)[3]), "r"((b)[0]), "r"((b)[1]))

// ---------------- HMMA bf16 split GEMM: C[m,n] = sum_k A[m,k]*B[n,k] --------
// BM=BN=128, BK=32, 256 thr (8 warps as 2m x 4n; warp tile 64x32).
// SMEM rows padded to 40 bf16 (80 B): 16B-unit stride 5 -> conflict-free ldmatrix.
#define BM 128
#define BN 128
#define BK 32
#define PITCH_B 80                       // bytes per smem row
#define TILE_BYTES (BM * PITCH_B)        // 10240 per split-tile
#define STAGE_BYTES (4 * TILE_BYTES)     // Ah Al Bh Bl
#define GEMM_SMEM (2 * STAGE_BYTES)      // 81920

__global__ void __launch_bounds__(256, 1)
k_gemm_mma(const __nv_bfloat16* __restrict__ Ah, const __nv_bfloat16* __restrict__ Al,
           const __nv_bfloat16* __restrict__ Bh, const __nv_bfloat16* __restrict__ Bl,
           float* __restrict__ C, int Ndim, int Kdim)
{
    extern __shared__ char sm[];
    const uint32_t sbase = smem_u32(sm);
    const int tid  = threadIdx.x;
    const int lane = tid & 31;
    const int wid  = tid >> 5;
    const int wm   = wid >> 2;            // 0..1
    const int wn   = wid & 3;             // 0..3
    const int rowBase = blockIdx.y * BM;
    const int colBase = blockIdx.x * BN;

    // per-thread cp.async coords: 2 chunks of 16B per split-tile
    const int cid0 = tid, cid1 = tid + 256;
    const int r0 = cid0 >> 2, c0 = cid0 & 3;
    const int r1 = cid1 >> 2, c1 = cid1 & 3;

    auto load_stage = [&](int s, int k0) {
        const uint32_t b = sbase + s * STAGE_BYTES;
        {
            uint32_t so = (uint32_t)(r0 * PITCH_B + c0 * 16);
            size_t ga = (size_t)(rowBase + r0) * Kdim + k0 + c0 * 8;
            size_t gb = (size_t)(colBase + r0) * Kdim + k0 + c0 * 8;
            CP_ASYNC16(b + so,                  Ah + ga);
            CP_ASYNC16(b + TILE_BYTES + so,     Al + ga);
            CP_ASYNC16(b + 2*TILE_BYTES + so,   Bh + gb);
            CP_ASYNC16(b + 3*TILE_BYTES + so,   Bl + gb);
        }
        {
            uint32_t so = (uint32_t)(r1 * PITCH_B + c1 * 16);
            size_t ga = (size_t)(rowBase + r1) * Kdim + k0 + c1 * 8;
            size_t gb = (size_t)(colBase + r1) * Kdim + k0 + c1 * 8;
            CP_ASYNC16(b + so,                  Ah + ga);
            CP_ASYNC16(b + TILE_BYTES + so,     Al + ga);
            CP_ASYNC16(b + 2*TILE_BYTES + so,   Bh + gb);
            CP_ASYNC16(b + 3*TILE_BYTES + so,   Bl + gb);
        }
        CP_COMMIT();
    };

    float acc[4][4][4];
    #pragma unroll
    for (int i = 0; i < 4; ++i)
        #pragma unroll
        for (int j = 0; j < 4; ++j)
            #pragma unroll
            for (int r = 0; r < 4; ++r) acc[i][j][r] = 0.f;

    const int niter = Kdim / BK;
    load_stage(0, 0);

    // ldmatrix lane addressing (within a tile, relative offsets)
    const int aRow = (lane & 15);                 // + mf*16 + wm*64
    const int aK   = ((lane >> 4) << 3);          // + kk
    const int bRow = (lane & 7);                  // + nf*8 + wn*32
    const int bK   = (((lane >> 3) & 1) << 3);    // + kk

    for (int it = 0; it < niter; ++it) {
        const int s = it & 1;
        if (it + 1 < niter) { load_stage(s ^ 1, (it + 1) * BK); CP_WAIT(1); }
        else                { CP_WAIT(0); }
        __syncthreads();

        const uint32_t tA0 = sbase + s * STAGE_BYTES;
        const uint32_t tA1 = tA0 + TILE_BYTES;
        const uint32_t tB0 = tA0 + 2 * TILE_BYTES;
        const uint32_t tB1 = tA0 + 3 * TILE_BYTES;

        #pragma unroll
        for (int kk = 0; kk < BK; kk += 16) {
            uint32_t ah[4][4], bh[4][2];
            #pragma unroll
            for (int mf = 0; mf < 4; ++mf) {
                uint32_t addr = tA0 + (uint32_t)((wm*64 + mf*16 + aRow) * PITCH_B + (kk + aK) * 2);
                LDMATRIX_X4(ah[mf], addr);
            }
            #pragma unroll
            for (int nf = 0; nf < 4; ++nf) {
                uint32_t addr = tB0 + (uint32_t)((wn*32 + nf*8 + bRow) * PITCH_B + (kk + bK) * 2);
                LDMATRIX_X2(bh[nf], addr);
            }
            #pragma unroll
            for (int mf = 0; mf < 4; ++mf)
                #pragma unroll
                for (int nf = 0; nf < 4; ++nf) MMA_BF16(acc[mf][nf], ah[mf], bh[nf]);

            // lo(A) * hi(B)
            #pragma unroll
            for (int mf = 0; mf < 4; ++mf) {
                uint32_t al[4];
                uint32_t addr = tA1 + (uint32_t)((wm*64 + mf*16 + aRow) * PITCH_B + (kk + aK) * 2);
                LDMATRIX_X4(al, addr);
                #pragma unroll
                for (int nf = 0; nf < 4; ++nf) MMA_BF16(acc[mf][nf], al, bh[nf]);
            }
            // hi(A) * lo(B)
            #pragma unroll
            for (int nf = 0; nf < 4; ++nf) {
                uint32_t bl[2];
                uint32_t addr = tB1 + (uint32_t)((wn*32 + nf*8 + bRow) * PITCH_B + (kk + bK) * 2);
                LDMATRIX_X2(bl, addr);
                #pragma unroll
                for (int mf = 0; mf < 4; ++mf) MMA_BF16(acc[mf][nf], ah[mf], bl);
            }
        }
        __syncthreads();
    }

    // epilogue: c0,c1 -> (row g, col 2*tig); c2,c3 -> (row g+8, same cols)
    const int gq  = lane >> 2;
    const int tig = lane & 3;
    #pragma unroll
    for (int mf = 0; mf < 4; ++mf) {
        const int row = rowBase + wm*64 + mf*16 + gq;
        #pragma unroll
        for (int nf = 0; nf < 4; ++nf) {
            const int col = colBase + wn*32 + nf*8 + 2*tig;
            *(float2*)(C + (size_t)row * Ndim + col)       = make_float2(acc[mf][nf][0], acc[mf][nf][1]);
            *(float2*)(C + (size_t)(row + 8) * Ndim + col) = make_float2(acc[mf][nf][2], acc[mf][nf][3]);
        }
    }
}

// ---------------- fp32 -> bf16 hi/lo split ----------------------------------
__global__ void __launch_bounds__(256)
k_split(const float* __restrict__ src, __nv_bfloat16* __restrict__ hi,
        __nv_bfloat16* __restrict__ lo)
{
    int i = (blockIdx.x * 256 + threadIdx.x) * 4;
    float4 v = *(const float4*)(src + i);
    union { __nv_bfloat16 b[4]; uint2 u; } H, L;
    float vv[4] = {v.x, v.y, v.z, v.w};
    #pragma unroll
    for (int j = 0; j < 4; ++j) {
        __nv_bfloat16 h = __float2bfloat16_rn(vv[j]);
        H.b[j] = h;
        L.b[j] = __float2bfloat16_rn(vv[j] - __bfloat162float(h));
    }
    *(uint2*)(hi + i) = H.u;
    *(uint2*)(lo + i) = L.u;
}

// ---------------- RoPE + scatter -------------------------------------------
__global__ void __launch_bounds__(256)
k_rope_q(const float* __restrict__ cosb, const float* __restrict__ sinb)
{
    int idx = blockIdx.x * blockDim.x + threadIdx.x;
    int j = idx & 63;
    int h = (idx >> 6) & 15;
    int t = idx >> 10;
    const float* base = g_qkv + t*QKV_DIM + (h >> 2)*768 + (h & 3)*128;
    float x1 = base[j], x2 = base[64 + j];
    float c = cosb[t*64 + j], s = sinb[t*64 + j];
    float* q = g_Q + (t*HEADS + h)*D_HEAD;
    q[j]      = (x1*c - x2*s) * SCALE_Q;
    q[64 + j] = (x1*s + x2*c) * SCALE_Q;
}

__global__ void __launch_bounds__(256)
k_rope_k(const float* __restrict__ cosb, const float* __restrict__ sinb)
{
    int idx = blockIdx.x * blockDim.x + threadIdx.x;
    int j = idx & 63;
    int g = (idx >> 6) & 3;
    int t = idx >> 8;
    const float* base = g_qkv + t*QKV_DIM + g*768 + 512;
    float x1 = base[j], x2 = base[64 + j];
    float c = cosb[t*64 + j], s = sinb[t*64 + j];
    float* k = g_K + (g*TK_ + t + 1)*D_HEAD;
    k[j]      = x1*c - x2*s;
    k[64 + j] = x1*s + x2*c;
}

__global__ void __launch_bounds__(256)
k_copy_v()
{
    int idx = blockIdx.x * blockDim.x + threadIdx.x;
    int d = idx & 127;
    int g = (idx >> 7) & 3;
    int t = idx >> 9;
    g_V[(g*TK_ + t + 1)*D_HEAD + d] = g_qkv[t*QKV_DIM + g*768 + 640 + d];
}

__global__ void __launch_bounds__(256)
k_sink(const float* __restrict__ k_sink, const float* __restrict__ v_sink)
{
    int idx = blockIdx.x * blockDim.x + threadIdx.x;
    if (idx >= GROUPS * D_HEAD) return;
    int g = idx >> 7;
    int d = idx & 127;
    g_K[(g*TK_)*D_HEAD + d] = k_sink[idx];
    g_V[(g*TK_)*D_HEAD + d] = v_sink[idx];
}

// ---------------- attention (unchanged, proven) ------------------------------
#define KCHUNK 32
__global__ void __launch_bounds__(256)
k_attn()
{
    __shared__ float Ks[KCHUNK][D_HEAD];
    __shared__ float Vs[KCHUNK][D_HEAD];

    const int h  = blockIdx.y;
    const int g  = h >> 2;
    const int i0 = blockIdx.x * 64;
    const int tid = threadIdx.x;
    const int qi  = tid >> 2;
    const int q4  = tid & 3;
    const int i   = i0 + qi;

    float qreg[32];
    {
        const float* qp = g_Q + (i*HEADS + h)*D_HEAD + q4;
        #pragma unroll
        for (int dd = 0; dd < 32; ++dd) qreg[dd] = qp[4*dd];
    }

    float acc[32] = {};
    float m = __int_as_float(0xff800000);
    float l = 0.f;

    const int lo  = max(0, i - 1022);
    const int hi  = i + 1;
    const int jlo = max(0, i0 - 1022);
    const int jhi = i0 + 64;

    const float* Kg = g_K + g*TK_*D_HEAD;
    const float* Vg = g_V + g*TK_*D_HEAD;

    for (int j0 = jlo; j0 <= jhi; j0 += KCHUNK) {
        const int jn = min(KCHUNK, jhi + 1 - j0);
        __syncthreads();
        for (int e = tid; e < jn * 32; e += 256) {
            int r = e >> 5, c = e & 31;
            ((float4*)&Ks[r][0])[c] = ((const float4*)(Kg + (j0 + r)*D_HEAD))[c];
            ((float4*)&Vs[r][0])[c] = ((const float4*)(Vg + (j0 + r)*D_HEAD))[c];
        }
        __syncthreads();

        for (int jj = 0; jj < jn; ++jj) {
            const int j = j0 + jj;
            float s = 0.f;
            const float* kr = &Ks[jj][q4];
            #pragma unroll
            for (int dd = 0; dd < 32; ++dd) s += qreg[dd] * kr[4*dd];
            s += __shfl_xor_sync(0xffffffffu, s, 1);
            s += __shfl_xor_sync(0xffffffffu, s, 2);

            if (j < lo || j > hi) continue;

            if (s > m) {
                float corr = __expf(m - s);
                l *= corr;
                #pragma unroll
                for (int dd = 0; dd < 32; ++dd) acc[dd] *= corr;
                m = s;
            }
            float p = __expf(s - m);
            l += p;
            const float* vr = &Vs[jj][q4];
            #pragma unroll
            for (int dd = 0; dd < 32; ++dd) acc[dd] += p * vr[4*dd];
        }
    }

    const float inv = 1.f / l;
    float* op = g_O + (i*HEADS + h)*D_HEAD + q4;
    #pragma unroll
    for (int dd = 0; dd < 32; ++dd) op[4*dd] = acc[dd] * inv;
}

// ---------------- launch -----------------------------------------------------
extern "C" void kernel_launch(void* const* d_in, const int* in_sizes, int n_in,
                              void* d_out, int out_size)
{
    const float* x      = (const float*)d_in[0];
    const float* cosb   = (const float*)d_in[1];
    const float* sinb   = (const float*)d_in[2];
    const float* W_attn = (const float*)d_in[3];
    const float* W_proj = (const float*)d_in[4];
    const float* ksink  = (const float*)d_in[5];
    const float* vsink  = (const float*)d_in[6];
    float* out = (float*)d_out;

    cudaFuncSetAttribute(k_gemm_mma, cudaFuncAttributeMaxDynamicSharedMemorySize,
                         GEMM_SMEM);

    __nv_bfloat16 *xh, *xl, *wah, *wal, *oh, *ol, *wph, *wpl;
    float *qkv, *O;
    cudaGetSymbolAddress((void**)&xh,  g_xh);  cudaGetSymbolAddress((void**)&xl,  g_xl);
    cudaGetSymbolAddress((void**)&wah, g_wah); cudaGetSymbolAddress((void**)&wal, g_wal);
    cudaGetSymbolAddress((void**)&oh,  g_oh);  cudaGetSymbolAddress((void**)&ol,  g_ol);
    cudaGetSymbolAddress((void**)&wph, g_wph); cudaGetSymbolAddress((void**)&wpl, g_wpl);
    cudaGetSymbolAddress((void**)&qkv, g_qkv); cudaGetSymbolAddress((void**)&O,   g_O);

    // 1) split inputs to bf16 hi/lo
    k_split<<<(C_DIM*C_DIM)/1024, 256>>>(x, xh, xl);
    k_split<<<(QKV_DIM*C_DIM)/1024, 256>>>(W_attn, wah, wal);

    // 2) qkv = x @ W_attn^T  (M=2048, N=3072, K=2048)
    k_gemm_mma<<<dim3(QKV_DIM/BN, T_SEQ/BM), 256, GEMM_SMEM>>>(
        xh, xl, wah, wal, qkv, QKV_DIM, C_DIM);

    // 3) RoPE + scatter; sink row
    k_rope_q<<<(T_SEQ*HEADS*64)/256, 256>>>(cosb, sinb);
    k_rope_k<<<(T_SEQ*GROUPS*64)/256, 256>>>(cosb, sinb);
    k_copy_v<<<(T_SEQ*GROUPS*128)/256, 256>>>();
    k_sink<<<2, 256>>>(ksink, vsink);

    // 4) attention
    k_attn<<<dim3(T_SEQ/64, HEADS), 256>>>();

    // 5) split O and W_proj; y = O @ W_proj^T  (M=2048, N=2048, K=2048)
    k_split<<<(T_SEQ*HEADS*D_HEAD)/1024, 256>>>(O, oh, ol);
    k_split<<<(C_DIM*HEADS*D_HEAD)/1024, 256>>>(W_proj, wph, wpl);
    k_gemm_mma<<<dim3(C_DIM/BN, T_SEQ/BM), 256, GEMM_SMEM>>>(
        oh, ol, wph, wpl, out, C_DIM, HEADS * D_HEAD);
}

// round 4
// speedup vs baseline: 3.5763x; 2.4036x over previous
#include <cuda_runtime.h>
#include <cuda_bf16.h>
#include <cstdint>

#define T_SEQ   2048
#define HEADS   16
#define GROUPS  4
#define D_HEAD  128
#define TK_     (T_SEQ + 1)
#define QKV_DIM 3072
#define C_DIM   2048
#define HD      (HEADS * D_HEAD)
#define SCALE_Q 0.08838834764831845f   // 1/sqrt(128)

// ---------------- scratch (device globals; no allocation allowed) ----------
__device__ float g_qkv[T_SEQ * QKV_DIM];

__device__ __align__(16) __nv_bfloat16 g_xh [C_DIM  * C_DIM];
__device__ __align__(16) __nv_bfloat16 g_xl [C_DIM  * C_DIM];
__device__ __align__(16) __nv_bfloat16 g_wah[QKV_DIM * C_DIM];
__device__ __align__(16) __nv_bfloat16 g_wal[QKV_DIM * C_DIM];
__device__ __align__(16) __nv_bfloat16 g_oh [T_SEQ * HD];
__device__ __align__(16) __nv_bfloat16 g_ol [T_SEQ * HD];
__device__ __align__(16) __nv_bfloat16 g_wph[C_DIM * HD];
__device__ __align__(16) __nv_bfloat16 g_wpl[C_DIM * HD];

// attention operands, bf16 hi/lo
__device__ __align__(16) __nv_bfloat16 g_qh [T_SEQ * HD];
__device__ __align__(16) __nv_bfloat16 g_ql [T_SEQ * HD];
__device__ __align__(16) __nv_bfloat16 g_kh [GROUPS * TK_ * D_HEAD];
__device__ __align__(16) __nv_bfloat16 g_kl [GROUPS * TK_ * D_HEAD];
__device__ __align__(16) __nv_bfloat16 g_vh [GROUPS * TK_ * D_HEAD];
__device__ __align__(16) __nv_bfloat16 g_vl [GROUPS * TK_ * D_HEAD];

// ---------------- low-level helpers -----------------------------------------
__device__ __forceinline__ uint32_t smem_u32(const void* p) {
    uint32_t a;
    asm("{ .reg .u64 t; cvta.to.shared.u64 t, %1; cvt.u32.u64 %0, t; }" : "=r"(a) : "l"(p));
    return a;
}
#define CP_ASYNC16(sm, gp) \
    asm volatile("cp.async.cg.shared.global [%0], [%1], 16;" :: "r"(sm), "l"(gp) : "memory")
#define CP_ASYNC16Z(sm, gp, sz) \
    asm volatile("cp.async.cg.shared.global [%0], [%1], 16, %2;" :: "r"(sm), "l"(gp), "r"(sz) : "memory")
#define CP_COMMIT() asm volatile("cp.async.commit_group;" ::: "memory")
#define CP_WAIT(n)  asm volatile("cp.async.wait_group %0;" :: "n"(n) : "memory")

#define LDMATRIX_X4(r, a) \
    asm volatile("ldmatrix.sync.aligned.m8n8.x4.shared.b16 {%0,%1,%2,%3}, [%4];" \
        : "=r"((r)[0]), "=r"((r)[1]), "=r"((r)[2]), "=r"((r)[3]) : "r"(a))
#define LDMATRIX_X2(r, a) \
    asm volatile("ldmatrix.sync.aligned.m8n8.x2.shared.b16 {%0,%1}, [%2];" \
        : "=r"((r)[0]), "=r"((r)[1]) : "r"(a))
#define LDMATRIX_X2T(r, a) \
    asm volatile("ldmatrix.sync.aligned.m8n8.x2.trans.shared.b16 {%0,%1}, [%2];" \
        : "=r"((r)[0]), "=r"((r)[1]) : "r"(a))

#define MMA_BF16(d, a, b) \
    asm volatile("mma.sync.aligned.m16n8k16.row.col.f32.bf16.bf16.f32 " \
        "{%0,%1,%2,%3},{%4,%5,%6,%7},{%8,%9},{%0,%1,%2,%3};" \
        : "+f"((d)[0]), "+f"((d)[1]), "+f"((d)[2]), "+f"((d)[3]) \
        : "r"((a)[0]), "r"((a)[1]), "r"((a)[2]), "r"((a)[3]), "r"((b)[0]), "r"((b)[1]))

__device__ __forceinline__ uint32_t pack_bf16(__nv_bfloat16 lo, __nv_bfloat16 hi) {
    __nv_bfloat162 t = __halves2bfloat162(lo, hi);      // x = lo, y = hi
    return *reinterpret_cast<uint32_t*>(&t);
}

// ---------------- HMMA bf16 split GEMM: C[m,n] = sum_k A[m,k]*B[n,k] --------
#define BM 128
#define BN 128
#define BK 32
#define PITCH_B 80
#define TILE_BYTES (BM * PITCH_B)
#define STAGE_BYTES (4 * TILE_BYTES)
#define GEMM_SMEM (2 * STAGE_BYTES)

__global__ void __launch_bounds__(256, 1)
k_gemm_mma(const __nv_bfloat16* __restrict__ Ah, const __nv_bfloat16* __restrict__ Al,
           const __nv_bfloat16* __restrict__ Bh, const __nv_bfloat16* __restrict__ Bl,
           float* __restrict__ C, int Ndim, int Kdim)
{
    extern __shared__ char sm[];
    const uint32_t sbase = smem_u32(sm);
    const int tid  = threadIdx.x;
    const int lane = tid & 31;
    const int wid  = tid >> 5;
    const int wm   = wid >> 2;
    const int wn   = wid & 3;
    const int rowBase = blockIdx.y * BM;
    const int colBase = blockIdx.x * BN;

    const int r0 = tid >> 2, c0 = tid & 3;
    const int r1 = (tid + 256) >> 2, c1 = (tid + 256) & 3;

    auto load_stage = [&](int s, int k0) {
        const uint32_t b = sbase + s * STAGE_BYTES;
        {
            uint32_t so = (uint32_t)(r0 * PITCH_B + c0 * 16);
            size_t ga = (size_t)(rowBase + r0) * Kdim + k0 + c0 * 8;
            size_t gb = (size_t)(colBase + r0) * Kdim + k0 + c0 * 8;
            CP_ASYNC16(b + so,                Ah + ga);
            CP_ASYNC16(b + TILE_BYTES + so,   Al + ga);
            CP_ASYNC16(b + 2*TILE_BYTES + so, Bh + gb);
            CP_ASYNC16(b + 3*TILE_BYTES + so, Bl + gb);
        }
        {
            uint32_t so = (uint32_t)(r1 * PITCH_B + c1 * 16);
            size_t ga = (size_t)(rowBase + r1) * Kdim + k0 + c1 * 8;
            size_t gb = (size_t)(colBase + r1) * Kdim + k0 + c1 * 8;
            CP_ASYNC16(b + so,                Ah + ga);
            CP_ASYNC16(b + TILE_BYTES + so,   Al + ga);
            CP_ASYNC16(b + 2*TILE_BYTES + so, Bh + gb);
            CP_ASYNC16(b + 3*TILE_BYTES + so, Bl + gb);
        }
        CP_COMMIT();
    };

    float acc[4][4][4];
    #pragma unroll
    for (int i = 0; i < 4; ++i)
        #pragma unroll
        for (int j = 0; j < 4; ++j)
            #pragma unroll
            for (int r = 0; r < 4; ++r) acc[i][j][r] = 0.f;

    const int niter = Kdim / BK;
    load_stage(0, 0);

    const int aRow = (lane & 15);
    const int aK   = ((lane >> 4) << 3);
    const int bRow = (lane & 7);
    const int bK   = (((lane >> 3) & 1) << 3);

    for (int it = 0; it < niter; ++it) {
        const int s = it & 1;
        if (it + 1 < niter) { load_stage(s ^ 1, (it + 1) * BK); CP_WAIT(1); }
        else                { CP_WAIT(0); }
        __syncthreads();

        const uint32_t tA0 = sbase + s * STAGE_BYTES;
        const uint32_t tA1 = tA0 + TILE_BYTES;
        const uint32_t tB0 = tA0 + 2 * TILE_BYTES;
        const uint32_t tB1 = tA0 + 3 * TILE_BYTES;

        #pragma unroll
        for (int kk = 0; kk < BK; kk += 16) {
            uint32_t ah[4][4], bh[4][2];
            #pragma unroll
            for (int mf = 0; mf < 4; ++mf) {
                uint32_t addr = tA0 + (uint32_t)((wm*64 + mf*16 + aRow) * PITCH_B + (kk + aK) * 2);
                LDMATRIX_X4(ah[mf], addr);
            }
            #pragma unroll
            for (int nf = 0; nf < 4; ++nf) {
                uint32_t addr = tB0 + (uint32_t)((wn*32 + nf*8 + bRow) * PITCH_B + (kk + bK) * 2);
                LDMATRIX_X2(bh[nf], addr);
            }
            #pragma unroll
            for (int mf = 0; mf < 4; ++mf)
                #pragma unroll
                for (int nf = 0; nf < 4; ++nf) MMA_BF16(acc[mf][nf], ah[mf], bh[nf]);

            #pragma unroll
            for (int mf = 0; mf < 4; ++mf) {
                uint32_t al[4];
                uint32_t addr = tA1 + (uint32_t)((wm*64 + mf*16 + aRow) * PITCH_B + (kk + aK) * 2);
                LDMATRIX_X4(al, addr);
                #pragma unroll
                for (int nf = 0; nf < 4; ++nf) MMA_BF16(acc[mf][nf], al, bh[nf]);
            }
            #pragma unroll
            for (int nf = 0; nf < 4; ++nf) {
                uint32_t bl[2];
                uint32_t addr = tB1 + (uint32_t)((wn*32 + nf*8 + bRow) * PITCH_B + (kk + bK) * 2);
                LDMATRIX_X2(bl, addr);
                #pragma unroll
                for (int mf = 0; mf < 4; ++mf) MMA_BF16(acc[mf][nf], ah[mf], bl);
            }
        }
        __syncthreads();
    }

    const int gq  = lane >> 2;
    const int tig = lane & 3;
    #pragma unroll
    for (int mf = 0; mf < 4; ++mf) {
        const int row = rowBase + wm*64 + mf*16 + gq;
        #pragma unroll
        for (int nf = 0; nf < 4; ++nf) {
            const int col = colBase + wn*32 + nf*8 + 2*tig;
            *(float2*)(C + (size_t)row * Ndim + col)       = make_float2(acc[mf][nf][0], acc[mf][nf][1]);
            *(float2*)(C + (size_t)(row + 8) * Ndim + col) = make_float2(acc[mf][nf][2], acc[mf][nf][3]);
        }
    }
}

// ---------------- fp32 -> bf16 hi/lo split ----------------------------------
__global__ void __launch_bounds__(256)
k_split(const float* __restrict__ src, __nv_bfloat16* __restrict__ hi,
        __nv_bfloat16* __restrict__ lo)
{
    int i = (blockIdx.x * 256 + threadIdx.x) * 4;
    float4 v = *(const float4*)(src + i);
    union { __nv_bfloat16 b[4]; uint2 u; } H, L;
    float vv[4] = {v.x, v.y, v.z, v.w};
    #pragma unroll
    for (int j = 0; j < 4; ++j) {
        __nv_bfloat16 h = __float2bfloat16_rn(vv[j]);
        H.b[j] = h;
        L.b[j] = __float2bfloat16_rn(vv[j] - __bfloat162float(h));
    }
    *(uint2*)(hi + i) = H.u;
    *(uint2*)(lo + i) = L.u;
}

// ---------------- RoPE + scatter, emitting bf16 hi/lo -----------------------
__device__ __forceinline__ void split_store(__nv_bfloat16* hi, __nv_bfloat16* lo,
                                            size_t idx, float v) {
    __nv_bfloat16 h = __float2bfloat16_rn(v);
    hi[idx] = h;
    lo[idx] = __float2bfloat16_rn(v - __bfloat162float(h));
}

__global__ void __launch_bounds__(256)
k_rope_q(const float* __restrict__ cosb, const float* __restrict__ sinb)
{
    int idx = blockIdx.x * blockDim.x + threadIdx.x;   // T*H*64
    int j = idx & 63;
    int h = (idx >> 6) & 15;
    int t = idx >> 10;
    const float* base = g_qkv + t*QKV_DIM + (h >> 2)*768 + (h & 3)*128;
    float x1 = base[j], x2 = base[64 + j];
    float c = cosb[t*64 + j], s = sinb[t*64 + j];
    size_t o = (size_t)t * HD + h * D_HEAD;
    split_store(g_qh, g_ql, o + j,      (x1*c - x2*s) * SCALE_Q);
    split_store(g_qh, g_ql, o + 64 + j, (x1*s + x2*c) * SCALE_Q);
}

__global__ void __launch_bounds__(256)
k_rope_k(const float* __restrict__ cosb, const float* __restrict__ sinb)
{
    int idx = blockIdx.x * blockDim.x + threadIdx.x;   // T*G*64
    int j = idx & 63;
    int g = (idx >> 6) & 3;
    int t = idx >> 8;
    const float* base = g_qkv + t*QKV_DIM + g*768 + 512;
    float x1 = base[j], x2 = base[64 + j];
    float c = cosb[t*64 + j], s = sinb[t*64 + j];
    size_t o = (size_t)(g*TK_ + t + 1) * D_HEAD;
    split_store(g_kh, g_kl, o + j,      x1*c - x2*s);
    split_store(g_kh, g_kl, o + 64 + j, x1*s + x2*c);
}

__global__ void __launch_bounds__(256)
k_copy_v()
{
    int idx = blockIdx.x * blockDim.x + threadIdx.x;   // T*G*128
    int d = idx & 127;
    int g = (idx >> 7) & 3;
    int t = idx >> 9;
    split_store(g_vh, g_vl, (size_t)(g*TK_ + t + 1) * D_HEAD + d,
                g_qkv[t*QKV_DIM + g*768 + 640 + d]);
}

__global__ void __launch_bounds__(256)
k_sink(const float* __restrict__ k_sink, const float* __restrict__ v_sink)
{
    int idx = blockIdx.x * blockDim.x + threadIdx.x;
    if (idx >= GROUPS * D_HEAD) return;
    int g = idx >> 7;
    int d = idx & 127;
    size_t o = (size_t)(g*TK_) * D_HEAD + d;
    split_store(g_kh, g_kl, o, k_sink[idx]);
    split_store(g_vh, g_vl, o, v_sink[idx]);
}

// ---------------- flash attention on HMMA ------------------------------------
// Block = (head, 128-query tile). 8 warps x 16 rows. 32-key chunks, double-buffered.
// S = (Qh+Ql)(Kh+Kl)^T via 3 passes; O += (Ph+Pl)(Vh+Vl) via 3 passes.
#define AT_CN    32
#define AT_PITCH 272                         // 128 bf16 * 2B + 16B pad (17 x 16B)
#define AT_TILE  (AT_CN * AT_PITCH)          // 8704
#define AT_STAGE (4 * AT_TILE)               // 34816
#define ATT_SMEM (2 * AT_STAGE)              // 69632

__global__ void __launch_bounds__(256, 1)
k_attn_mma()
{
    extern __shared__ char sm[];
    const uint32_t sbase = smem_u32(sm);
    const int tid  = threadIdx.x;
    const int lane = tid & 31;
    const int wq   = tid >> 5;
    const int gq   = lane >> 2;
    const int tig  = lane & 3;

    const int h  = blockIdx.y;
    const int g  = h >> 2;
    const int i0 = blockIdx.x * 128;

    const __nv_bfloat16* Kgh = g_kh + (size_t)g * TK_ * D_HEAD;
    const __nv_bfloat16* Kgl = g_kl + (size_t)g * TK_ * D_HEAD;
    const __nv_bfloat16* Vgh = g_vh + (size_t)g * TK_ * D_HEAD;
    const __nv_bfloat16* Vgl = g_vl + (size_t)g * TK_ * D_HEAD;

    // ---- Q fragments (hi/lo) resident in registers ----
    const int iA = i0 + wq*16 + gq;       // row of c0/c1
    const int iB = iA + 8;                // row of c2/c3
    uint32_t Qh[8][4], Ql[8][4];
    {
        const size_t r0 = (size_t)iA * HD + h * D_HEAD;
        const size_t r1 = (size_t)iB * HD + h * D_HEAD;
        #pragma unroll
        for (int kf = 0; kf < 8; ++kf) {
            const int col = kf*16 + tig*2;
            Qh[kf][0] = *(const uint32_t*)(g_qh + r0 + col);
            Qh[kf][1] = *(const uint32_t*)(g_qh + r1 + col);
            Qh[kf][2] = *(const uint32_t*)(g_qh + r0 + col + 8);
            Qh[kf][3] = *(const uint32_t*)(g_qh + r1 + col + 8);
            Ql[kf][0] = *(const uint32_t*)(g_ql + r0 + col);
            Ql[kf][1] = *(const uint32_t*)(g_ql + r1 + col);
            Ql[kf][2] = *(const uint32_t*)(g_ql + r0 + col + 8);
            Ql[kf][3] = *(const uint32_t*)(g_ql + r1 + col + 8);
        }
    }

    float O[16][4];
    #pragma unroll
    for (int i = 0; i < 16; ++i)
        #pragma unroll
        for (int r = 0; r < 4; ++r) O[i][r] = 0.f;
    float mA = -__int_as_float(0x7f800000) * 0.f - 1e38f;  // effectively -inf surrogate
    mA = __int_as_float(0xff800000);
    float mB = __int_as_float(0xff800000);
    float lA = 0.f, lB = 0.f;

    const int jlo = max(0, i0 - 1022);
    const int jhi = i0 + 128;                 // inclusive; <= 2048
    const int nchunk = (jhi - jlo + AT_CN) / AT_CN;

    const int loA = iA - 1022, hiA = iA + 1;
    const int loB = iB - 1022, hiB = iB + 1;

    auto load_chunk = [&](int s, int j0) {
        #pragma unroll
        for (int t = 0; t < 8; ++t) {
            const int tensor = t >> 1;                // 0:Kh 1:Kl 2:Vh 3:Vl
            const int inner  = tid + (t & 1) * 256;   // 0..511
            const int row = inner >> 4, c16 = inner & 15;
            int j = j0 + row;
            uint32_t sz = (j <= 2048) ? 16u : 0u;
            if (j > 2048) j = 2048;
            uint32_t dst = sbase + s*AT_STAGE + tensor*AT_TILE
                         + (uint32_t)(row*AT_PITCH + c16*16);
            const __nv_bfloat16* base =
                (tensor == 0) ? Kgh : (tensor == 1) ? Kgl : (tensor == 2) ? Vgh : Vgl;
            CP_ASYNC16Z(dst, base + (size_t)j * D_HEAD + c16*8, sz);
        }
        CP_COMMIT();
    };

    load_chunk(0, jlo);

    for (int c = 0; c < nchunk; ++c) {
        const int s  = c & 1;
        const int j0 = jlo + c * AT_CN;
        if (c + 1 < nchunk) { load_chunk(s ^ 1, j0 + AT_CN); CP_WAIT(1); }
        else                { CP_WAIT(0); }
        __syncthreads();

        const uint32_t bKh = sbase + s*AT_STAGE;
        const uint32_t bKl = bKh + AT_TILE;
        const uint32_t bVh = bKh + 2*AT_TILE;
        const uint32_t bVl = bKh + 3*AT_TILE;

        // ---- S = Q K^T (3 passes) ----
        float S[4][4];
        const int kRow = lane & 7;
        const int kOff = ((lane >> 3) & 1) * 16;
        #pragma unroll
        for (int nf = 0; nf < 4; ++nf) {
            #pragma unroll
            for (int r = 0; r < 4; ++r) S[nf][r] = 0.f;
            #pragma unroll
            for (int kf = 0; kf < 8; ++kf) {
                uint32_t b[2];
                uint32_t rowoff = (uint32_t)((nf*8 + kRow) * AT_PITCH + kf*32 + kOff);
                LDMATRIX_X2(b, bKh + rowoff);
                MMA_BF16(S[nf], Qh[kf], b);
                MMA_BF16(S[nf], Ql[kf], b);
                LDMATRIX_X2(b, bKl + rowoff);
                MMA_BF16(S[nf], Qh[kf], b);
            }
        }

        // ---- mask + online softmax ----
        float mcA = __int_as_float(0xff800000), mcB = __int_as_float(0xff800000);
        #pragma unroll
        for (int nf = 0; nf < 4; ++nf) {
            const int j = j0 + nf*8 + tig*2;
            #pragma unroll
            for (int e = 0; e < 2; ++e) {
                const int jj = j + e;
                if (jj < loA || jj > hiA) S[nf][e] = __int_as_float(0xff800000);
                mcA = fmaxf(mcA, S[nf][e]);
                if (jj < loB || jj > hiB) S[nf][2+e] = __int_as_float(0xff800000);
                mcB = fmaxf(mcB, S[nf][2+e]);
            }
        }
        mcA = fmaxf(mcA, __shfl_xor_sync(0xffffffffu, mcA, 1));
        mcA = fmaxf(mcA, __shfl_xor_sync(0xffffffffu, mcA, 2));
        mcB = fmaxf(mcB, __shfl_xor_sync(0xffffffffu, mcB, 1));
        mcB = fmaxf(mcB, __shfl_xor_sync(0xffffffffu, mcB, 2));

        const float mAn = fmaxf(mA, mcA);
        const float mBn = fmaxf(mB, mcB);
        const float baseA = fmaxf(mAn, -1e30f);
        const float baseB = fmaxf(mBn, -1e30f);
        const float corrA = __expf(mA - baseA);   // mA = -inf -> 0
        const float corrB = __expf(mB - baseB);
        mA = mAn; mB = mBn;
        lA *= corrA; lB *= corrB;
        #pragma unroll
        for (int i = 0; i < 16; ++i) {
            O[i][0] *= corrA; O[i][1] *= corrA;
            O[i][2] *= corrB; O[i][3] *= corrB;
        }

        uint32_t Ph[2][4], Pl[2][4];
        #pragma unroll
        for (int nf = 0; nf < 4; ++nf) {
            float p0 = __expf(S[nf][0] - baseA);
            float p1 = __expf(S[nf][1] - baseA);
            float p2 = __expf(S[nf][2] - baseB);
            float p3 = __expf(S[nf][3] - baseB);
            lA += p0 + p1; lB += p2 + p3;
            __nv_bfloat16 h0 = __float2bfloat16_rn(p0);
            __nv_bfloat16 h1 = __float2bfloat16_rn(p1);
            __nv_bfloat16 h2 = __float2bfloat16_rn(p2);
            __nv_bfloat16 h3 = __float2bfloat16_rn(p3);
            const int kf2 = nf >> 1, half = (nf & 1) * 2;
            Ph[kf2][half + 0] = pack_bf16(h0, h1);
            Ph[kf2][half + 1] = pack_bf16(h2, h3);
            Pl[kf2][half + 0] = pack_bf16(__float2bfloat16_rn(p0 - __bfloat162float(h0)),
                                          __float2bfloat16_rn(p1 - __bfloat162float(h1)));
            Pl[kf2][half + 1] = pack_bf16(__float2bfloat16_rn(p2 - __bfloat162float(h2)),
                                          __float2bfloat16_rn(p3 - __bfloat162float(h3)));
        }

        // ---- O += P V (3 passes) ----
        const int vRow = (lane & 7) + ((lane >> 3) & 1) * 8;
        #pragma unroll
        for (int nf2 = 0; nf2 < 16; ++nf2) {
            #pragma unroll
            for (int kf2 = 0; kf2 < 2; ++kf2) {
                uint32_t b[2];
                uint32_t off = (uint32_t)((kf2*16 + vRow) * AT_PITCH + nf2*16);
                LDMATRIX_X2T(b, bVh + off);
                MMA_BF16(O[nf2], Ph[kf2], b);
                MMA_BF16(O[nf2], Pl[kf2], b);
                LDMATRIX_X2T(b, bVl + off);
                MMA_BF16(O[nf2], Ph[kf2], b);
            }
        }
        __syncthreads();
    }

    // ---- epilogue: normalize, split to bf16 hi/lo, store ----
    lA += __shfl_xor_sync(0xffffffffu, lA, 1);
    lA += __shfl_xor_sync(0xffffffffu, lA, 2);
    lB += __shfl_xor_sync(0xffffffffu, lB, 1);
    lB += __shfl_xor_sync(0xffffffffu, lB, 2);
    const float invA = 1.f / lA;
    const float invB = 1.f / lB;

    const size_t rA = (size_t)iA * HD + h * D_HEAD;
    const size_t rB = (size_t)iB * HD + h * D_HEAD;
    #pragma unroll
    for (int nf2 = 0; nf2 < 16; ++nf2) {
        const int col = nf2*8 + tig*2;
        float v0 = O[nf2][0] * invA, v1 = O[nf2][1] * invA;
        float v2 = O[nf2][2] * invB, v3 = O[nf2][3] * invB;
        __nv_bfloat16 h0 = __float2bfloat16_rn(v0), h1 = __float2bfloat16_rn(v1);
        __nv_bfloat16 h2 = __float2bfloat16_rn(v2), h3 = __float2bfloat16_rn(v3);
        *(uint32_t*)(g_oh + rA + col) = pack_bf16(h0, h1);
        *(uint32_t*)(g_oh + rB + col) = pack_bf16(h2, h3);
        *(uint32_t*)(g_ol + rA + col) = pack_bf16(__float2bfloat16_rn(v0 - __bfloat162float(h0)),
                                                  __float2bfloat16_rn(v1 - __bfloat162float(h1)));
        *(uint32_t*)(g_ol + rB + col) = pack_bf16(__float2bfloat16_rn(v2 - __bfloat162float(h2)),
                                                  __float2bfloat16_rn(v3 - __bfloat162float(h3)));
    }
}

// ---------------- launch -----------------------------------------------------
extern "C" void kernel_launch(void* const* d_in, const int* in_sizes, int n_in,
                              void* d_out, int out_size)
{
    const float* x      = (const float*)d_in[0];
    const float* cosb   = (const float*)d_in[1];
    const float* sinb   = (const float*)d_in[2];
    const float* W_attn = (const float*)d_in[3];
    const float* W_proj = (const float*)d_in[4];
    const float* ksink  = (const float*)d_in[5];
    const float* vsink  = (const float*)d_in[6];
    float* out = (float*)d_out;

    cudaFuncSetAttribute(k_gemm_mma, cudaFuncAttributeMaxDynamicSharedMemorySize, GEMM_SMEM);
    cudaFuncSetAttribute(k_attn_mma, cudaFuncAttributeMaxDynamicSharedMemorySize, ATT_SMEM);

    __nv_bfloat16 *xh, *xl, *wah, *wal, *oh, *ol, *wph, *wpl;
    float *qkv;
    cudaGetSymbolAddress((void**)&xh,  g_xh);  cudaGetSymbolAddress((void**)&xl,  g_xl);
    cudaGetSymbolAddress((void**)&wah, g_wah); cudaGetSymbolAddress((void**)&wal, g_wal);
    cudaGetSymbolAddress((void**)&oh,  g_oh);  cudaGetSymbolAddress((void**)&ol,  g_ol);
    cudaGetSymbolAddress((void**)&wph, g_wph); cudaGetSymbolAddress((void**)&wpl, g_wpl);
    cudaGetSymbolAddress((void**)&qkv, g_qkv);

    // 1) split inputs to bf16 hi/lo
    k_split<<<(C_DIM*C_DIM)/1024, 256>>>(x, xh, xl);
    k_split<<<(QKV_DIM*C_DIM)/1024, 256>>>(W_attn, wah, wal);

    // 2) qkv = x @ W_attn^T
    k_gemm_mma<<<dim3(QKV_DIM/BN, T_SEQ/BM), 256, GEMM_SMEM>>>(
        xh, xl, wah, wal, qkv, QKV_DIM, C_DIM);

    // 3) RoPE + scatter -> bf16 hi/lo Q/K/V; sink row
    k_rope_q<<<(T_SEQ*HEADS*64)/256, 256>>>(cosb, sinb);
    k_rope_k<<<(T_SEQ*GROUPS*64)/256, 256>>>(cosb, sinb);
    k_copy_v<<<(T_SEQ*GROUPS*128)/256, 256>>>();
    k_sink<<<2, 256>>>(ksink, vsink);

    // 4) flash attention on tensor cores -> oh/ol directly
    k_attn_mma<<<dim3(T_SEQ/128, HEADS), 256, ATT_SMEM>>>();

    // 5) y = O @ W_proj^T
    k_split<<<(C_DIM*HD)/1024, 256>>>(W_proj, wph, wpl);
    k_gemm_mma<<<dim3(C_DIM/BN, T_SEQ/BM), 256, GEMM_SMEM>>>(
        oh, ol, wph, wpl, out, C_DIM, HD);
}